// round 1
// baseline (speedup 1.0000x reference)
#include <cuda_runtime.h>
#include <math.h>

// Problem constants
#define NN 256
#define BATCH 4096
#define N_MZIS 32640  // 256*255/2

// Scratch (no allocations allowed): per-MZI coefficients and Re(U)
__device__ float4 g_coef[N_MZIS];          // (cos th, sin th*cos ph, sin th*sin ph, 0)
__device__ float  g_W[NN * NN];            // W[i][j] = Re(e^{i phe_i} * Uscan[i][j])

// ---------------------------------------------------------------------------
// Kernel A: per-MZI coefficients
// ---------------------------------------------------------------------------
__global__ void coef_kernel(const float* __restrict__ theta,
                            const float* __restrict__ phi) {
    int i = blockIdx.x * blockDim.x + threadIdx.x;
    if (i < N_MZIS) {
        float s, c;
        sincosf(theta[i], &s, &c);
        float ei, er;
        sincosf(phi[i], &ei, &er);
        g_coef[i] = make_float4(c, s * er, s * ei, 0.0f);
    }
}

// ---------------------------------------------------------------------------
// Kernel B: build one column of U per CTA via systolic wavefront.
// MZI (layer l, pos p) runs at wavefront time t = 2l + p.
// At fixed t, active row pairs (p, p+1) are disjoint (p spaced by 2).
// Depth = 2N-4 = 508 steps instead of 32640.
// ---------------------------------------------------------------------------
__global__ __launch_bounds__(128, 8) void build_u_kernel(const float* __restrict__ phi_ext) {
    __shared__ float2 v[NN];  // column j of U (complex)
    const int j = blockIdx.x;
    const int tid = threadIdx.x;  // 128 threads

    // init column = e_j
    for (int r = tid; r < NN; r += 128)
        v[r] = make_float2(r == j ? 1.0f : 0.0f, 0.0f);
    __syncthreads();

    #pragma unroll 1
    for (int t = 0; t <= 2 * NN - 4; ++t) {
        int lmin = t - (NN - 2);
        if (lmin < 0) lmin = 0;
        const int lmax = t >> 1;
        const int l = lmin + tid;
        if (l <= lmax) {
            const int p = t - 2 * l;
            // layer offset: l*(N-1) - l*(l-1)/2
            const int idx = l * (NN - 1) - ((l * (l - 1)) >> 1) + p;
            const float4 cf = __ldg(&g_coef[idx]);
            const float c = cf.x, sr = cf.y, si = cf.z;
            const float2 v0 = v[p];
            const float2 v1 = v[p + 1];
            // new0 = c*v0 - s*conj(e)*v1 ; new1 = s*e*v0 + c*v1
            float2 n0, n1;
            n0.x = c * v0.x - sr * v1.x - si * v1.y;
            n0.y = c * v0.y - sr * v1.y + si * v1.x;
            n1.x = sr * v0.x - si * v0.y + c * v1.x;
            n1.y = sr * v0.y + si * v0.x + c * v1.y;
            v[p]     = n0;
            v[p + 1] = n1;
        }
        __syncthreads();
    }

    // external phase screen, keep only real part:
    // Re(e^{i phe} * (a+ib)) = a*cos(phe) - b*sin(phe)
    for (int r = tid; r < NN; r += 128) {
        float sp, cp;
        sincosf(phi_ext[r], &sp, &cp);
        g_W[r * NN + j] = cp * v[r].x - sp * v[r].y;
    }
}

// ---------------------------------------------------------------------------
// Kernel C: out[b,i] = sum_j x[b,j] * W[i,j]   (fp32 tiled GEMM, NT-style)
// BM=BN=64, BK=16, 256 threads, 4x4 per thread.
// ---------------------------------------------------------------------------
#define BM 64
#define BN 64
#define BK 16

__global__ __launch_bounds__(256, 4) void gemm_kernel(const float* __restrict__ A,
                                                      float* __restrict__ C) {
    __shared__ float As[BK][BM + 1];
    __shared__ float Ws[BK][BN + 1];

    const int tid = threadIdx.x;
    const int tx = tid & 15;        // 0..15 -> n tile
    const int ty = tid >> 4;        // 0..15 -> m tile
    const int bm0 = blockIdx.x * BM;
    const int bn0 = blockIdx.y * BN;

    const int lr = tid >> 2;         // 0..63 tile row for loading
    const int lc = (tid & 3) * 4;    // 0,4,8,12 k offset for loading

    float acc[4][4] = {};

    for (int k0 = 0; k0 < NN; k0 += BK) {
        const float4 a4 = *reinterpret_cast<const float4*>(A + (bm0 + lr) * NN + k0 + lc);
        const float4 w4 = *reinterpret_cast<const float4*>(g_W + (bn0 + lr) * NN + k0 + lc);
        As[lc + 0][lr] = a4.x; As[lc + 1][lr] = a4.y;
        As[lc + 2][lr] = a4.z; As[lc + 3][lr] = a4.w;
        Ws[lc + 0][lr] = w4.x; Ws[lc + 1][lr] = w4.y;
        Ws[lc + 2][lr] = w4.z; Ws[lc + 3][lr] = w4.w;
        __syncthreads();

        #pragma unroll
        for (int k = 0; k < BK; ++k) {
            float am[4], bn[4];
            #pragma unroll
            for (int i = 0; i < 4; ++i) am[i] = As[k][ty * 4 + i];
            #pragma unroll
            for (int i = 0; i < 4; ++i) bn[i] = Ws[k][tx * 4 + i];
            #pragma unroll
            for (int i = 0; i < 4; ++i)
                #pragma unroll
                for (int jj = 0; jj < 4; ++jj)
                    acc[i][jj] = fmaf(am[i], bn[jj], acc[i][jj]);
        }
        __syncthreads();
    }

    #pragma unroll
    for (int i = 0; i < 4; ++i) {
        float4 r = make_float4(acc[i][0], acc[i][1], acc[i][2], acc[i][3]);
        *reinterpret_cast<float4*>(C + (bm0 + ty * 4 + i) * NN + bn0 + tx * 4) = r;
    }
}

// ---------------------------------------------------------------------------
// Launch: inputs (metadata order): x, theta, phi_internal, phi_external
// ---------------------------------------------------------------------------
extern "C" void kernel_launch(void* const* d_in, const int* in_sizes, int n_in,
                              void* d_out, int out_size) {
    const float* x       = (const float*)d_in[0];
    const float* theta   = (const float*)d_in[1];
    const float* phi_int = (const float*)d_in[2];
    const float* phi_ext = (const float*)d_in[3];
    float* out = (float*)d_out;

    coef_kernel<<<(N_MZIS + 255) / 256, 256>>>(theta, phi_int);
    build_u_kernel<<<NN, 128>>>(phi_ext);
    gemm_kernel<<<dim3(BATCH / BM, NN / BN), 256>>>(x, out);
}

// round 3
// speedup vs baseline: 1.0198x; 1.0198x over previous
#include <cuda_runtime.h>
#include <math.h>

#define NN 256
#define BATCH 4096
#define N_MZIS 32640   // 256*255/2
#define STEPS 509      // wavefront depth: t = 0..508

// Scratch (no allocations allowed)
__device__ float4 g_coef[N_MZIS];        // (cos th, sin th*cos ph, sin th*sin ph, 0)
__device__ float  g_Wt[NN * NN];         // g_Wt[j*NN + i] = Re(e^{i phe_i} * Uscan[i][j])

// ---------------------------------------------------------------------------
// Kernel A: per-MZI coefficients
// ---------------------------------------------------------------------------
__global__ void coef_kernel(const float* __restrict__ theta,
                            const float* __restrict__ phi) {
    int i = blockIdx.x * blockDim.x + threadIdx.x;
    if (i < N_MZIS) {
        float s, c;
        sincosf(theta[i], &s, &c);
        float ei, er;
        sincosf(phi[i], &ei, &er);
        g_coef[i] = make_float4(c, s * er, s * ei, 0.0f);
    }
}

// ---------------------------------------------------------------------------
// Kernel B: build 2 columns of U per CTA via systolic wavefront.
// Thread tid owns layer tid (phase 1), then layer tid+128 (phase 2); the two
// active intervals are disjoint. Within a layer, position p increments by 1
// per wavefront step, so:
//   - row p+1's new value (n1) is the thread's own v0 next step  -> register carry
//   - coefficient indices are contiguous -> 2-deep prefetch pipeline
// Per step: 1x LDS.128 + 1x STS.128 + FMAs + barrier. No LDG on critical path.
// Columns j0, j0+1 interleaved as float4 {re0, im0, re1, im1}.
// ---------------------------------------------------------------------------
__global__ __launch_bounds__(128, 1) void build_u_kernel(const float* __restrict__ phi_ext) {
    __shared__ float4 v[NN];
    const int tid = threadIdx.x;
    const int j0 = blockIdx.x * 2;

    // init columns = e_j0, e_j1
    for (int r = tid; r < NN; r += 128) {
        v[r] = make_float4(r == j0 ? 1.0f : 0.0f, 0.0f,
                           r == j0 + 1 ? 1.0f : 0.0f, 0.0f);
    }

    // phase-1 state: layer l = tid
    int l = tid;
    int pmax = 254 - l;
    int base = l * 255 - ((l * (l - 1)) >> 1);
    float4 cfA = __ldg(&g_coef[base]);
    float4 cfB = (pmax >= 1) ? __ldg(&g_coef[base + 1]) : cfA;
    float4 v0 = make_float4(0.0f, 0.0f, 0.0f, 0.0f);
    __syncthreads();

    #pragma unroll 1
    for (int t = 0; t < STEPS; ++t) {
        const int p = t - 2 * l;
        if (p >= 0 && p <= pmax) {
            if (p == 0) v0 = v[0];
            const float4 v1 = v[p + 1];
            const float c = cfA.x, sr = cfA.y, si = cfA.z;
            // advance coefficient pipeline (off critical path)
            cfA = cfB;
            if (p + 2 <= pmax) cfB = __ldg(&g_coef[base + p + 2]);

            float4 n0, n1;
            n0.x = c * v0.x - sr * v1.x - si * v1.y;
            n0.y = c * v0.y - sr * v1.y + si * v1.x;
            n0.z = c * v0.z - sr * v1.z - si * v1.w;
            n0.w = c * v0.w - sr * v1.w + si * v1.z;
            n1.x = sr * v0.x - si * v0.y + c * v1.x;
            n1.y = sr * v0.y + si * v0.x + c * v1.y;
            n1.z = sr * v0.z - si * v0.w + c * v1.z;
            n1.w = sr * v0.w + si * v0.z + c * v1.w;
            v[p] = n0;
            v0 = n1;                       // register carry: next step's row p+1
            if (p == pmax) v[p + 1] = n1;  // layer's last MZI: row p+1 is final
        }
        // phase-2 preload: one step after phase-1 ends (t = tid + 255),
        // entry at t = 2*tid + 256 => >= tid+1 steps of prefetch lead.
        if (t == tid + 255 && tid < 127) {
            l = tid + 128;
            pmax = 254 - l;
            base = l * 255 - ((l * (l - 1)) >> 1);
            cfA = __ldg(&g_coef[base]);
            cfB = (pmax >= 1) ? __ldg(&g_coef[base + 1]) : cfA;
        }
        __syncthreads();
    }

    // external phase screen, real part only; coalesced store (W transposed)
    for (int r = tid; r < NN; r += 128) {
        float sp, cp;
        sincosf(__ldg(&phi_ext[r]), &sp, &cp);
        const float4 val = v[r];
        g_Wt[j0 * NN + r]       = cp * val.x - sp * val.y;
        g_Wt[(j0 + 1) * NN + r] = cp * val.z - sp * val.w;
    }
}

// ---------------------------------------------------------------------------
// Kernel C: out[b,i] = sum_j x[b,j] * Wt[j,i]
// BM=BN=64, BK=16, 256 threads, 4x4 per thread, float4 smem paths (pad +4).
// ---------------------------------------------------------------------------
#define BM 64
#define BN 64
#define BK 16

__global__ __launch_bounds__(256, 4) void gemm_kernel(const float* __restrict__ A,
                                                      float* __restrict__ C) {
    __shared__ float As[BK][BM + 4];
    __shared__ float Ws[BK][BN + 4];

    const int tid = threadIdx.x;
    const int tx = tid & 15;         // n sub-tile
    const int ty = tid >> 4;         // m sub-tile
    const int bm0 = blockIdx.x * BM;
    const int bn0 = blockIdx.y * BN;

    // A loading: thread -> (row lr in 0..63, k offset lc in {0,4,8,12})
    const int lr = tid >> 2;
    const int lc = (tid & 3) * 4;
    // W loading: thread -> (k row wr in 0..15, i offset wc in {0..60 step 4})
    const int wr = tid >> 4;
    const int wc = (tid & 15) * 4;

    float acc[4][4] = {};

    for (int k0 = 0; k0 < NN; k0 += BK) {
        const float4 a4 = *reinterpret_cast<const float4*>(A + (bm0 + lr) * NN + k0 + lc);
        As[lc + 0][lr] = a4.x; As[lc + 1][lr] = a4.y;
        As[lc + 2][lr] = a4.z; As[lc + 3][lr] = a4.w;
        const float4 w4 = *reinterpret_cast<const float4*>(g_Wt + (k0 + wr) * NN + bn0 + wc);
        *reinterpret_cast<float4*>(&Ws[wr][wc]) = w4;
        __syncthreads();

        #pragma unroll
        for (int k = 0; k < BK; ++k) {
            const float4 am = *reinterpret_cast<const float4*>(&As[k][ty * 4]);
            const float4 bn = *reinterpret_cast<const float4*>(&Ws[k][tx * 4]);
            const float a[4] = {am.x, am.y, am.z, am.w};
            const float b[4] = {bn.x, bn.y, bn.z, bn.w};
            #pragma unroll
            for (int i = 0; i < 4; ++i)
                #pragma unroll
                for (int jj = 0; jj < 4; ++jj)
                    acc[i][jj] = fmaf(a[i], b[jj], acc[i][jj]);
        }
        __syncthreads();
    }

    #pragma unroll
    for (int i = 0; i < 4; ++i) {
        float4 r = make_float4(acc[i][0], acc[i][1], acc[i][2], acc[i][3]);
        *reinterpret_cast<float4*>(C + (bm0 + ty * 4 + i) * NN + bn0 + tx * 4) = r;
    }
}

// ---------------------------------------------------------------------------
// Launch: inputs (metadata order): x, theta, phi_internal, phi_external
// ---------------------------------------------------------------------------
extern "C" void kernel_launch(void* const* d_in, const int* in_sizes, int n_in,
                              void* d_out, int out_size) {
    const float* x       = (const float*)d_in[0];
    const float* theta   = (const float*)d_in[1];
    const float* phi_int = (const float*)d_in[2];
    const float* phi_ext = (const float*)d_in[3];
    float* out = (float*)d_out;

    coef_kernel<<<(N_MZIS + 255) / 256, 256>>>(theta, phi_int);
    build_u_kernel<<<NN / 2, 128>>>(phi_ext);
    gemm_kernel<<<dim3(BATCH / BM, NN / BN), 256>>>(x, out);
}